// round 13
// baseline (speedup 1.0000x reference)
#include <cuda_runtime.h>
#include <cuda_fp16.h>
#include <cstdint>

// ============================================================================
// Problem constants
// ============================================================================
#define BATCH   4
#define SEQ     4096
#define DMODEL  1024
#define DK      64
#define ROWS    (BATCH * SEQ)        // 16384

// Projected tensors. q folded with mask*0.125*log2(e) -> logits in base-2.
__device__ __align__(16) __half g_qh [ROWS * DK];
__device__ __align__(16) __half g_kh [ROWS * DK];
__device__ __align__(16) __half g_vh [ROWS * DK];

// Pre-converted weights (hi/lo fp16), 3 projections flat
__device__ __align__(16) __half g_Whi[3 * DMODEL * DK];
__device__ __align__(16) __half g_Wlo[3 * DMODEL * DK];

// split-K attention scratch: 4 quarters write disjoint buffers (deterministic)
#define ZSPLIT 4
__device__ float g_Oacc[ZSPLIT][ROWS * DK];
__device__ float g_Lacc[ZSPLIT][ROWS];

// ============================================================================
// small helpers
// ============================================================================
__device__ __forceinline__ uint32_t cvta_smem(const void* p) {
    return (uint32_t)__cvta_generic_to_shared(p);
}

#define LDSM_X4(r0, r1, r2, r3, addr) \
    asm volatile("ldmatrix.sync.aligned.m8n8.x4.shared.b16 {%0,%1,%2,%3}, [%4];" \
        : "=r"(r0), "=r"(r1), "=r"(r2), "=r"(r3) : "r"(addr))

#define LDSM_X4_T(r0, r1, r2, r3, addr) \
    asm volatile("ldmatrix.sync.aligned.m8n8.x4.trans.shared.b16 {%0,%1,%2,%3}, [%4];" \
        : "=r"(r0), "=r"(r1), "=r"(r2), "=r"(r3) : "r"(addr))

#define MMA16816(d, a, b0, b1) \
    asm volatile("mma.sync.aligned.m16n8k16.row.col.f32.f16.f16.f32 " \
        "{%0,%1,%2,%3}, {%4,%5,%6,%7}, {%8,%9}, {%0,%1,%2,%3};" \
        : "+f"((d)[0]), "+f"((d)[1]), "+f"((d)[2]), "+f"((d)[3]) \
        : "r"((a)[0]), "r"((a)[1]), "r"((a)[2]), "r"((a)[3]), "r"(b0), "r"(b1))

#define CP_ASYNC16(dst, src) \
    asm volatile("cp.async.cg.shared.global [%0], [%1], 16;" \
        :: "r"(dst), "l"(src) : "memory")
#define CP_COMMIT()  asm volatile("cp.async.commit_group;" ::: "memory")
#define CP_WAIT0()   asm volatile("cp.async.wait_group 0;" ::: "memory")

// 2-wide exp2 on packed f16
#define EX2_F16X2(dst, src) \
    asm volatile("ex2.approx.f16x2 %0, %1;" : "=r"(dst) : "r"(src))

__device__ __forceinline__ uint32_t pack_h2(float a, float b) {
    __half2 h = __floats2half2_rn(a, b);
    return *reinterpret_cast<uint32_t*>(&h);
}

// smem swizzle: row-major fp16 tiles, row = 128B = 8 chunks of 16B.
__device__ __forceinline__ uint32_t sw_off(int row, int chunk) {
    return (uint32_t)(row * 128 + ((chunk ^ (row & 7)) << 4));
}

// ============================================================================
// Weight pre-conversion: fp32 -> fp16 hi + lo residual, once.
// ============================================================================
__global__ __launch_bounds__(256) void wconv_kernel(
    const float* __restrict__ Wq, const float* __restrict__ Wk,
    const float* __restrict__ Wv)
{
    int i = blockIdx.x * 256 + threadIdx.x;
    int which = blockIdx.y;
    const float* W = (which == 0) ? Wq : (which == 1) ? Wk : Wv;
    float v = W[i];
    __half h = __float2half_rn(v);
    g_Whi[which * DMODEL * DK + i] = h;
    g_Wlo[which * DMODEL * DK + i] = __float2half_rn(v - __half2float(h));
}

// ============================================================================
// q/k projection: plain fp16 GEMM. (unchanged from R12)
// ============================================================================
#define PJ_TILE 8192
#define QK_SMEM (4 * PJ_TILE)
#define QK_XHI(s) ((s) * PJ_TILE)
#define QK_WHI(s) (16384 + (s) * PJ_TILE)

__global__ __launch_bounds__(128) void proj_qk_kernel(
    const float* __restrict__ Xq, const float* __restrict__ Xk,
    const float* __restrict__ bq, const float* __restrict__ bk,
    const float* __restrict__ mask)
{
    extern __shared__ __align__(16) char psm[];
    const uint32_t sbase = cvta_smem(psm);

    const int tid   = threadIdx.x;
    const int lane  = tid & 31;
    const int w     = tid >> 5;
    const int which = blockIdx.y;
    const int row0  = blockIdx.x * 64;
    const int g     = lane >> 2;
    const int t     = lane & 3;
    const int qq    = lane >> 3;
    const int rr    = lane & 7;

    const float* X    = (which == 0) ? Xq : Xk;
    const float* bias = (which == 0) ? bq : bk;
    const __half* Whi = g_Whi + which * DMODEL * DK;

    const int sr[4] = { (tid) >> 3, (tid + 128) >> 3, (tid + 256) >> 3, (tid + 384) >> 3 };
    const int sc    = tid & 7;

    float O[8][4];
#pragma unroll
    for (int j = 0; j < 8; j++)
#pragma unroll
        for (int i = 0; i < 4; i++) O[j][i] = 0.f;

    float4 xa[4], xb[4];
#pragma unroll
    for (int i = 0; i < 4; i++) {
        const float* src = X + (size_t)(row0 + sr[i]) * DMODEL + sc * 8;
        xa[i] = *reinterpret_cast<const float4*>(src);
        xb[i] = *reinterpret_cast<const float4*>(src + 4);
    }
#pragma unroll
    for (int i = 0; i < 4; i++)
        CP_ASYNC16(sbase + QK_WHI(0) + sw_off(sr[i], sc),
                   Whi + (size_t)sr[i] * DK + sc * 8);
    CP_COMMIT();

    for (int kc = 0; kc < DMODEL / 64; kc++) {
        const int s = kc & 1;
        const int k0 = kc * 64;

#pragma unroll
        for (int i = 0; i < 4; i++) {
            float4 a = xa[i], b = xb[i];
            uint4 hv;
            hv.x = pack_h2(a.x, a.y);
            hv.y = pack_h2(a.z, a.w);
            hv.z = pack_h2(b.x, b.y);
            hv.w = pack_h2(b.z, b.w);
            *reinterpret_cast<uint4*>(psm + QK_XHI(s) + sw_off(sr[i], sc)) = hv;
        }
        if (kc + 1 < DMODEL / 64) {
#pragma unroll
            for (int i = 0; i < 4; i++) {
                const float* src = X + (size_t)(row0 + sr[i]) * DMODEL
                                     + (k0 + 64) + sc * 8;
                xa[i] = *reinterpret_cast<const float4*>(src);
                xb[i] = *reinterpret_cast<const float4*>(src + 4);
            }
        }

        CP_WAIT0();
        __syncthreads();

        if (kc + 1 < DMODEL / 64) {
#pragma unroll
            for (int i = 0; i < 4; i++)
                CP_ASYNC16(sbase + QK_WHI(s ^ 1) + sw_off(sr[i], sc),
                           Whi + (size_t)(k0 + 64 + sr[i]) * DK + sc * 8);
            CP_COMMIT();
        }

        uint32_t aHi[4][4];
        {
            int arow = w * 16 + (qq & 1) * 8 + rr;
#pragma unroll
            for (int ss = 0; ss < 4; ss++) {
                uint32_t off = sw_off(arow, 2 * ss + (qq >> 1));
                LDSM_X4(aHi[ss][0], aHi[ss][1], aHi[ss][2], aHi[ss][3],
                        sbase + QK_XHI(s) + off);
            }
        }
        int brow_base = qq * 8 + rr;
#pragma unroll
        for (int j = 0; j < 8; j++) {
#pragma unroll
            for (int sp = 0; sp < 2; sp++) {
                int brow = 32 * sp + brow_base;
                uint32_t v0, v1, v2, v3;
                LDSM_X4_T(v0, v1, v2, v3, sbase + QK_WHI(s) + sw_off(brow, j));
                MMA16816(O[j], aHi[2 * sp],     v0, v1);
                MMA16816(O[j], aHi[2 * sp + 1], v2, v3);
            }
        }
    }

    const int row_a = row0 + w * 16 + g;
    const int row_b = row_a + 8;
    const float LOG2E_O8 = 0.125f * 1.4426950408889634f;
    const float sca = (which == 0) ? (mask[row_a] * LOG2E_O8) : 1.0f;
    const float scb = (which == 0) ? (mask[row_b] * LOG2E_O8) : 1.0f;
    __half* Y = (which == 0) ? g_qh : g_kh;
#pragma unroll
    for (int j = 0; j < 8; j++) {
        int col = 8 * j + 2 * t;
        float b0 = bias[col], b1 = bias[col + 1];
        *reinterpret_cast<uint32_t*>(&Y[(size_t)row_a * DK + col]) =
            pack_h2((O[j][0] + b0) * sca, (O[j][1] + b1) * sca);
        *reinterpret_cast<uint32_t*>(&Y[(size_t)row_b * DK + col]) =
            pack_h2((O[j][2] + b0) * scb, (O[j][3] + b1) * scb);
    }
}

// ============================================================================
// v projection: split-fp16 3-MMA. (unchanged from R12)
// ============================================================================
#define PJ_SMEM (8 * PJ_TILE)
#define OFF_XHI(s) ((s) * PJ_TILE)
#define OFF_XLO(s) (16384 + (s) * PJ_TILE)
#define OFF_WHI(s) (32768 + (s) * PJ_TILE)
#define OFF_WLO(s) (49152 + (s) * PJ_TILE)

__global__ __launch_bounds__(128) void proj_v_kernel(
    const float* __restrict__ Xv, const float* __restrict__ bv)
{
    extern __shared__ __align__(16) char psm[];
    const uint32_t sbase = cvta_smem(psm);

    const int tid  = threadIdx.x;
    const int lane = tid & 31;
    const int w    = tid >> 5;
    const int row0 = blockIdx.x * 64;
    const int g    = lane >> 2;
    const int t    = lane & 3;
    const int qq   = lane >> 3;
    const int rr   = lane & 7;

    const __half* Whi = g_Whi + 2 * DMODEL * DK;
    const __half* Wlo = g_Wlo + 2 * DMODEL * DK;

    const int sr[4] = { (tid) >> 3, (tid + 128) >> 3, (tid + 256) >> 3, (tid + 384) >> 3 };
    const int sc    = tid & 7;

    float O[8][4];
#pragma unroll
    for (int j = 0; j < 8; j++)
#pragma unroll
        for (int i = 0; i < 4; i++) O[j][i] = 0.f;

    float4 xa[4], xb[4];
#pragma unroll
    for (int i = 0; i < 4; i++) {
        const float* src = Xv + (size_t)(row0 + sr[i]) * DMODEL + sc * 8;
        xa[i] = *reinterpret_cast<const float4*>(src);
        xb[i] = *reinterpret_cast<const float4*>(src + 4);
    }
#pragma unroll
    for (int i = 0; i < 4; i++) {
        uint32_t so = sw_off(sr[i], sc);
        CP_ASYNC16(sbase + OFF_WHI(0) + so, Whi + (size_t)sr[i] * DK + sc * 8);
        CP_ASYNC16(sbase + OFF_WLO(0) + so, Wlo + (size_t)sr[i] * DK + sc * 8);
    }
    CP_COMMIT();

    for (int kc = 0; kc < DMODEL / 64; kc++) {
        const int s = kc & 1;
        const int k0 = kc * 64;

#pragma unroll
        for (int i = 0; i < 4; i++) {
            float4 a = xa[i], b = xb[i];
            __half h[8];
            h[0]=__float2half_rn(a.x); h[1]=__float2half_rn(a.y);
            h[2]=__float2half_rn(a.z); h[3]=__float2half_rn(a.w);
            h[4]=__float2half_rn(b.x); h[5]=__float2half_rn(b.y);
            h[6]=__float2half_rn(b.z); h[7]=__float2half_rn(b.w);
            uint4 hv, lv;
            hv.x = pack_h2(__half2float(h[0]), __half2float(h[1]));
            hv.y = pack_h2(__half2float(h[2]), __half2float(h[3]));
            hv.z = pack_h2(__half2float(h[4]), __half2float(h[5]));
            hv.w = pack_h2(__half2float(h[6]), __half2float(h[7]));
            lv.x = pack_h2(a.x - __half2float(h[0]), a.y - __half2float(h[1]));
            lv.y = pack_h2(a.z - __half2float(h[2]), a.w - __half2float(h[3]));
            lv.z = pack_h2(b.x - __half2float(h[4]), b.y - __half2float(h[5]));
            lv.w = pack_h2(b.z - __half2float(h[6]), b.w - __half2float(h[7]));
            uint32_t so = sw_off(sr[i], sc);
            *reinterpret_cast<uint4*>(psm + OFF_XHI(s) + so) = hv;
            *reinterpret_cast<uint4*>(psm + OFF_XLO(s) + so) = lv;
        }
        if (kc + 1 < DMODEL / 64) {
#pragma unroll
            for (int i = 0; i < 4; i++) {
                const float* src = Xv + (size_t)(row0 + sr[i]) * DMODEL
                                      + (k0 + 64) + sc * 8;
                xa[i] = *reinterpret_cast<const float4*>(src);
                xb[i] = *reinterpret_cast<const float4*>(src + 4);
            }
        }

        CP_WAIT0();
        __syncthreads();

        if (kc + 1 < DMODEL / 64) {
#pragma unroll
            for (int i = 0; i < 4; i++) {
                uint32_t so = sw_off(sr[i], sc);
                CP_ASYNC16(sbase + OFF_WHI(s ^ 1) + so,
                           Whi + (size_t)(k0 + 64 + sr[i]) * DK + sc * 8);
                CP_ASYNC16(sbase + OFF_WLO(s ^ 1) + so,
                           Wlo + (size_t)(k0 + 64 + sr[i]) * DK + sc * 8);
            }
            CP_COMMIT();
        }

        uint32_t aHi[4][4], aLo[4][4];
        {
            int arow = w * 16 + (qq & 1) * 8 + rr;
#pragma unroll
            for (int ss = 0; ss < 4; ss++) {
                uint32_t off = sw_off(arow, 2 * ss + (qq >> 1));
                LDSM_X4(aHi[ss][0], aHi[ss][1], aHi[ss][2], aHi[ss][3],
                        sbase + OFF_XHI(s) + off);
                LDSM_X4(aLo[ss][0], aLo[ss][1], aLo[ss][2], aLo[ss][3],
                        sbase + OFF_XLO(s) + off);
            }
        }
        int brow_base = qq * 8 + rr;
#pragma unroll
        for (int j = 0; j < 8; j++) {
#pragma unroll
            for (int sp = 0; sp < 2; sp++) {
                int brow = 32 * sp + brow_base;
                uint32_t v0, v1, v2, v3, u0, u1, u2, u3;
                LDSM_X4_T(v0, v1, v2, v3, sbase + OFF_WHI(s) + sw_off(brow, j));
                MMA16816(O[j], aHi[2 * sp],     v0, v1);
                MMA16816(O[j], aHi[2 * sp + 1], v2, v3);
                MMA16816(O[j], aLo[2 * sp],     v0, v1);
                MMA16816(O[j], aLo[2 * sp + 1], v2, v3);
                LDSM_X4_T(u0, u1, u2, u3, sbase + OFF_WLO(s) + sw_off(brow, j));
                MMA16816(O[j], aHi[2 * sp],     u0, u1);
                MMA16816(O[j], aHi[2 * sp + 1], u2, u3);
            }
        }
    }

    const int row_a = row0 + w * 16 + g;
    const int row_b = row_a + 8;
#pragma unroll
    for (int j = 0; j < 8; j++) {
        int col = 8 * j + 2 * t;
        float b0 = bv[col], b1 = bv[col + 1];
        *reinterpret_cast<uint32_t*>(&g_vh[(size_t)row_a * DK + col]) =
            pack_h2(O[j][0] + b0, O[j][1] + b1);
        *reinterpret_cast<uint32_t*>(&g_vh[(size_t)row_b * DK + col]) =
            pack_h2(O[j][2] + b0, O[j][3] + b1);
    }
}

// ============================================================================
// FlashAttention, BR=128: each warp owns 32 query rows (2 m16 groups).
// K/V fragments loaded ONCE per warp and reused by both groups -> LDSM:MMA
// ratio halves (was the L1=65% binding pipe).
// ============================================================================
#define BR   128
#define BC   64
#define NKT_Z (SEQ / BC / ZSPLIT)      // 16 tiles per quarter

#define Q_BYTES     (BR * 128)                      // 16KB
#define TILE_BYTES  (BC * 128)
#define STAGE_BYTES (2 * TILE_BYTES)                // K + V = 16KB
#define ATTN_SMEM   (Q_BYTES + 2 * STAGE_BYTES)     // 49152

__device__ __forceinline__ void prefetch_tile(char* stage, int b, int key0, int tid)
{
    const __half* srcs[2] = {g_kh, g_vh};
#pragma unroll
    for (int i = 0; i < 8; i++) {
        int idx = tid + i * 128;
        int arr = idx >> 9;
        int rem = idx & 511;
        int row = rem >> 3, c = rem & 7;
        const __half* g = srcs[arr] + ((size_t)b * SEQ + key0 + row) * DK + c * 8;
        uint32_t d = cvta_smem(stage + arr * TILE_BYTES) + sw_off(row, c);
        CP_ASYNC16(d, g);
    }
}

__global__ __launch_bounds__(128, 3) void attn_kernel()
{
    extern __shared__ char smem[];
    char* Qs = smem;
    char* St = smem + Q_BYTES;

    const int tid  = threadIdx.x;
    const int lane = tid & 31;
    const int w    = tid >> 5;
    const int b    = blockIdx.y;
    const int q0   = blockIdx.x * BR;
    const int z    = blockIdx.z;
    const int key_base = z * (SEQ / ZSPLIT);
    const int g    = lane >> 2;
    const int t    = lane & 3;
    const int qq   = lane >> 3;
    const int rr   = lane & 7;

    prefetch_tile(St, b, key_base, tid);
    CP_COMMIT();

    // stage Q tile (128 rows)
    {
        const __half* qb = g_qh + ((size_t)b * SEQ + q0) * DK;
#pragma unroll
        for (int i = 0; i < 8; i++) {
            int idx = tid + i * 128;
            int row = idx >> 3, c = idx & 7;
            uint4 v = *reinterpret_cast<const uint4*>(qb + (size_t)row * DK + c * 8);
            *reinterpret_cast<uint4*>(Qs + sw_off(row, c)) = v;
        }
    }
    __syncthreads();

    // Q A-fragments for both 16-row groups
    uint32_t qA[2][4][4];
    {
        uint32_t qbase = cvta_smem(Qs);
#pragma unroll
        for (int grp = 0; grp < 2; grp++) {
            int row = w * 32 + grp * 16 + (qq & 1) * 8 + rr;
#pragma unroll
            for (int s = 0; s < 4; s++) {
                uint32_t addr = qbase + sw_off(row, 2 * s + (qq >> 1));
                LDSM_X4(qA[grp][s][0], qA[grp][s][1],
                        qA[grp][s][2], qA[grp][s][3], addr);
            }
        }
    }

    float O0[8][4], O1[8][4];
#pragma unroll
    for (int j = 0; j < 8; j++)
#pragma unroll
        for (int i = 0; i < 4; i++) { O0[j][i] = 0.f; O1[j][i] = 0.f; }
    float OL0[4] = {0.f, 0.f, 0.f, 0.f};
    float OL1[4] = {0.f, 0.f, 0.f, 0.f};
    const uint32_t ONE2 = 0x3C003C00u;

    for (int kt = 0; kt < NKT_Z; kt++) {
        const int s = kt & 1;
        char* stage = St + s * STAGE_BYTES;

        CP_WAIT0();
        __syncthreads();

        if (kt + 1 < NKT_Z) {
            prefetch_tile(St + (s ^ 1) * STAGE_BYTES, b,
                          key_base + (kt + 1) * BC, tid);
            CP_COMMIT();
        }

        const uint32_t kb  = cvta_smem(stage);
        const uint32_t vhb = kb + TILE_BYTES;

        // ---- S both groups; K fragment loaded once, used twice ----
        uint32_t aP0[4][4], aP1[4][4];
#pragma unroll
        for (int j = 0; j < 8; j++) {
            float d0[4] = {0.f, 0.f, 0.f, 0.f};
            float d1[4] = {0.f, 0.f, 0.f, 0.f};
#pragma unroll
            for (int sp = 0; sp < 2; sp++) {
                int row = j * 8 + rr;
                uint32_t addr = kb + sw_off(row, 4 * sp + qq);
                uint32_t k0, k1, k2, k3;
                LDSM_X4(k0, k1, k2, k3, addr);
                MMA16816(d0, qA[0][2 * sp],     k0, k1);
                MMA16816(d0, qA[0][2 * sp + 1], k2, k3);
                MMA16816(d1, qA[1][2 * sp],     k0, k1);
                MMA16816(d1, qA[1][2 * sp + 1], k2, k3);
            }
            int sp2 = j >> 1, o = (j & 1) * 2;
            uint32_t p;
            EX2_F16X2(p, pack_h2(d0[0], d0[1])); aP0[sp2][o]     = p;
            EX2_F16X2(p, pack_h2(d0[2], d0[3])); aP0[sp2][o + 1] = p;
            EX2_F16X2(p, pack_h2(d1[0], d1[1])); aP1[sp2][o]     = p;
            EX2_F16X2(p, pack_h2(d1[2], d1[3])); aP1[sp2][o + 1] = p;
        }

        // ---- L via ones-B MMA (both groups) ----
        MMA16816(OL0, aP0[0], ONE2, ONE2);
        MMA16816(OL0, aP0[1], ONE2, ONE2);
        MMA16816(OL0, aP0[2], ONE2, ONE2);
        MMA16816(OL0, aP0[3], ONE2, ONE2);
        MMA16816(OL1, aP1[0], ONE2, ONE2);
        MMA16816(OL1, aP1[1], ONE2, ONE2);
        MMA16816(OL1, aP1[2], ONE2, ONE2);
        MMA16816(OL1, aP1[3], ONE2, ONE2);

        // ---- O += P @ V; V fragment loaded once, used twice ----
#pragma unroll
        for (int j = 0; j < 8; j++) {
#pragma unroll
            for (int sp = 0; sp < 2; sp++) {
                int row = 32 * sp + qq * 8 + rr;
                uint32_t v0, v1, v2, v3;
                LDSM_X4_T(v0, v1, v2, v3, vhb + sw_off(row, j));
                MMA16816(O0[j], aP0[2 * sp],     v0, v1);
                MMA16816(O0[j], aP0[2 * sp + 1], v2, v3);
                MMA16816(O1[j], aP1[2 * sp],     v0, v1);
                MMA16816(O1[j], aP1[2 * sp + 1], v2, v3);
            }
        }
    }

    // ---- epilogue: 4 row slots per thread ----
    const size_t rbase = (size_t)b * SEQ + q0 + w * 32 + g;
    float* Oz = g_Oacc[z];
    if (t == 0) {
        g_Lacc[z][rbase]      = OL0[0];
        g_Lacc[z][rbase + 8]  = OL0[2];
        g_Lacc[z][rbase + 16] = OL1[0];
        g_Lacc[z][rbase + 24] = OL1[2];
    }
#pragma unroll
    for (int j = 0; j < 8; j++) {
        int col = 8 * j + 2 * t;
        *reinterpret_cast<float2*>(Oz + (rbase)      * DK + col) =
            make_float2(O0[j][0], O0[j][1]);
        *reinterpret_cast<float2*>(Oz + (rbase + 8)  * DK + col) =
            make_float2(O0[j][2], O0[j][3]);
        *reinterpret_cast<float2*>(Oz + (rbase + 16) * DK + col) =
            make_float2(O1[j][0], O1[j][1]);
        *reinterpret_cast<float2*>(Oz + (rbase + 24) * DK + col) =
            make_float2(O1[j][2], O1[j][3]);
    }
}

// ============================================================================
// Normalize: out = sum_z O_z / sum_z L_z
// ============================================================================
__global__ __launch_bounds__(256) void normalize_kernel(float* __restrict__ out)
{
    int i = blockIdx.x * 256 + threadIdx.x;
    int row = i >> 4;
    float Lsum = 0.f;
#pragma unroll
    for (int z = 0; z < ZSPLIT; z++) Lsum += g_Lacc[z][row];
    float inv = 1.0f / Lsum;
    float4 r = make_float4(0.f, 0.f, 0.f, 0.f);
#pragma unroll
    for (int z = 0; z < ZSPLIT; z++) {
        float4 a = *reinterpret_cast<const float4*>(&g_Oacc[z][(size_t)i * 4]);
        r.x += a.x; r.y += a.y; r.z += a.z; r.w += a.w;
    }
    r.x *= inv; r.y *= inv; r.z *= inv; r.w *= inv;
    *reinterpret_cast<float4*>(out + (size_t)i * 4) = r;
}

// ============================================================================
// Stream/event infra (module load; streams/events only — no device memory)
// ============================================================================
static cudaStream_t g_s2   = nullptr;
static cudaEvent_t  g_fork = nullptr;
static cudaEvent_t  g_join = nullptr;
static const bool g_infra_init = []() {
    cudaStreamCreateWithFlags(&g_s2, cudaStreamNonBlocking);
    cudaEventCreateWithFlags(&g_fork, cudaEventDisableTiming);
    cudaEventCreateWithFlags(&g_join, cudaEventDisableTiming);
    return true;
}();

// ============================================================================
extern "C" void kernel_launch(void* const* d_in, const int* in_sizes, int n_in,
                              void* d_out, int out_size)
{
    const float* q  = (const float*)d_in[0];
    const float* k  = (const float*)d_in[1];
    const float* v  = (const float*)d_in[2];
    const float* m  = (const float*)d_in[3];
    const float* Wq = (const float*)d_in[4];
    const float* bq = (const float*)d_in[5];
    const float* Wk = (const float*)d_in[6];
    const float* bk = (const float*)d_in[7];
    const float* Wv = (const float*)d_in[8];
    const float* bv = (const float*)d_in[9];
    float* out = (float*)d_out;

    cudaFuncSetAttribute(proj_qk_kernel,
                         cudaFuncAttributeMaxDynamicSharedMemorySize, QK_SMEM);
    cudaFuncSetAttribute(proj_v_kernel,
                         cudaFuncAttributeMaxDynamicSharedMemorySize, PJ_SMEM);
    cudaFuncSetAttribute(attn_kernel,
                         cudaFuncAttributeMaxDynamicSharedMemorySize, ATTN_SMEM);

    dim3 wgrid(DMODEL * DK / 256, 3);
    wconv_kernel<<<wgrid, 256>>>(Wq, Wk, Wv);

    cudaEventRecord(g_fork, 0);
    cudaStreamWaitEvent(g_s2, g_fork, 0);

    proj_v_kernel<<<ROWS / 64, 128, PJ_SMEM, g_s2>>>(v, bv);
    cudaEventRecord(g_join, g_s2);

    dim3 qkgrid(ROWS / 64, 2);
    proj_qk_kernel<<<qkgrid, 128, QK_SMEM>>>(q, k, bq, bk, m);

    cudaStreamWaitEvent(0, g_join, 0);

    dim3 grid(SEQ / BR, BATCH, ZSPLIT);
    attn_kernel<<<grid, 128, ATTN_SMEM>>>();

    normalize_kernel<<<ROWS * DK / 4 / 256, 256>>>(out);
}

// round 14
// speedup vs baseline: 1.0432x; 1.0432x over previous
#include <cuda_runtime.h>
#include <cuda_fp16.h>
#include <cstdint>

// ============================================================================
// Problem constants
// ============================================================================
#define BATCH   4
#define SEQ     4096
#define DMODEL  1024
#define DK      64
#define ROWS    (BATCH * SEQ)        // 16384

// Projected tensors. q folded with mask*0.125*log2(e) -> logits in base-2.
__device__ __align__(16) __half g_qh [ROWS * DK];
__device__ __align__(16) __half g_kh [ROWS * DK];
__device__ __align__(16) __half g_vh [ROWS * DK];

// Pre-converted weights (hi/lo fp16), 3 projections flat
__device__ __align__(16) __half g_Whi[3 * DMODEL * DK];
__device__ __align__(16) __half g_Wlo[3 * DMODEL * DK];

// split-K attention scratch: 4 quarters write disjoint buffers (deterministic)
#define ZSPLIT 4
__device__ float g_Oacc[ZSPLIT][ROWS * DK];
__device__ float g_Lacc[ZSPLIT][ROWS];

// ============================================================================
// small helpers
// ============================================================================
__device__ __forceinline__ uint32_t cvta_smem(const void* p) {
    return (uint32_t)__cvta_generic_to_shared(p);
}

#define LDSM_X4(r0, r1, r2, r3, addr) \
    asm volatile("ldmatrix.sync.aligned.m8n8.x4.shared.b16 {%0,%1,%2,%3}, [%4];" \
        : "=r"(r0), "=r"(r1), "=r"(r2), "=r"(r3) : "r"(addr))

#define LDSM_X4_T(r0, r1, r2, r3, addr) \
    asm volatile("ldmatrix.sync.aligned.m8n8.x4.trans.shared.b16 {%0,%1,%2,%3}, [%4];" \
        : "=r"(r0), "=r"(r1), "=r"(r2), "=r"(r3) : "r"(addr))

#define MMA16816(d, a, b0, b1) \
    asm volatile("mma.sync.aligned.m16n8k16.row.col.f32.f16.f16.f32 " \
        "{%0,%1,%2,%3}, {%4,%5,%6,%7}, {%8,%9}, {%0,%1,%2,%3};" \
        : "+f"((d)[0]), "+f"((d)[1]), "+f"((d)[2]), "+f"((d)[3]) \
        : "r"((a)[0]), "r"((a)[1]), "r"((a)[2]), "r"((a)[3]), "r"(b0), "r"(b1))

// f16-accumulate MMA: d is 2 packed f16x2 regs {row_g cols}, {row_g+8 cols}
#define MMA16816_F16(d, a, b0, b1) \
    asm volatile("mma.sync.aligned.m16n8k16.row.col.f16.f16.f16.f16 " \
        "{%0,%1}, {%2,%3,%4,%5}, {%6,%7}, {%0,%1};" \
        : "+r"((d)[0]), "+r"((d)[1]) \
        : "r"((a)[0]), "r"((a)[1]), "r"((a)[2]), "r"((a)[3]), "r"(b0), "r"(b1))

#define CP_ASYNC16(dst, src) \
    asm volatile("cp.async.cg.shared.global [%0], [%1], 16;" \
        :: "r"(dst), "l"(src) : "memory")
#define CP_COMMIT()  asm volatile("cp.async.commit_group;" ::: "memory")
#define CP_WAIT0()   asm volatile("cp.async.wait_group 0;" ::: "memory")

// 2-wide exp2 on packed f16
#define EX2_F16X2(dst, src) \
    asm volatile("ex2.approx.f16x2 %0, %1;" : "=r"(dst) : "r"(src))

__device__ __forceinline__ uint32_t pack_h2(float a, float b) {
    __half2 h = __floats2half2_rn(a, b);
    return *reinterpret_cast<uint32_t*>(&h);
}

// smem swizzle: row-major fp16 tiles, row = 128B = 8 chunks of 16B.
__device__ __forceinline__ uint32_t sw_off(int row, int chunk) {
    return (uint32_t)(row * 128 + ((chunk ^ (row & 7)) << 4));
}

// ============================================================================
// Weight pre-conversion: fp32 -> fp16 hi + lo residual, once.
// ============================================================================
__global__ __launch_bounds__(256) void wconv_kernel(
    const float* __restrict__ Wq, const float* __restrict__ Wk,
    const float* __restrict__ Wv)
{
    int i = blockIdx.x * 256 + threadIdx.x;
    int which = blockIdx.y;
    const float* W = (which == 0) ? Wq : (which == 1) ? Wk : Wv;
    float v = W[i];
    __half h = __float2half_rn(v);
    g_Whi[which * DMODEL * DK + i] = h;
    g_Wlo[which * DMODEL * DK + i] = __float2half_rn(v - __half2float(h));
}

// ============================================================================
// q/k projection: plain fp16 GEMM. (R12, unchanged)
// ============================================================================
#define PJ_TILE 8192
#define QK_SMEM (4 * PJ_TILE)
#define QK_XHI(s) ((s) * PJ_TILE)
#define QK_WHI(s) (16384 + (s) * PJ_TILE)

__global__ __launch_bounds__(128) void proj_qk_kernel(
    const float* __restrict__ Xq, const float* __restrict__ Xk,
    const float* __restrict__ bq, const float* __restrict__ bk,
    const float* __restrict__ mask)
{
    extern __shared__ __align__(16) char psm[];
    const uint32_t sbase = cvta_smem(psm);

    const int tid   = threadIdx.x;
    const int lane  = tid & 31;
    const int w     = tid >> 5;
    const int which = blockIdx.y;
    const int row0  = blockIdx.x * 64;
    const int g     = lane >> 2;
    const int t     = lane & 3;
    const int qq    = lane >> 3;
    const int rr    = lane & 7;

    const float* X    = (which == 0) ? Xq : Xk;
    const float* bias = (which == 0) ? bq : bk;
    const __half* Whi = g_Whi + which * DMODEL * DK;

    const int sr[4] = { (tid) >> 3, (tid + 128) >> 3, (tid + 256) >> 3, (tid + 384) >> 3 };
    const int sc    = tid & 7;

    float O[8][4];
#pragma unroll
    for (int j = 0; j < 8; j++)
#pragma unroll
        for (int i = 0; i < 4; i++) O[j][i] = 0.f;

    float4 xa[4], xb[4];
#pragma unroll
    for (int i = 0; i < 4; i++) {
        const float* src = X + (size_t)(row0 + sr[i]) * DMODEL + sc * 8;
        xa[i] = *reinterpret_cast<const float4*>(src);
        xb[i] = *reinterpret_cast<const float4*>(src + 4);
    }
#pragma unroll
    for (int i = 0; i < 4; i++)
        CP_ASYNC16(sbase + QK_WHI(0) + sw_off(sr[i], sc),
                   Whi + (size_t)sr[i] * DK + sc * 8);
    CP_COMMIT();

    for (int kc = 0; kc < DMODEL / 64; kc++) {
        const int s = kc & 1;
        const int k0 = kc * 64;

#pragma unroll
        for (int i = 0; i < 4; i++) {
            float4 a = xa[i], b = xb[i];
            uint4 hv;
            hv.x = pack_h2(a.x, a.y);
            hv.y = pack_h2(a.z, a.w);
            hv.z = pack_h2(b.x, b.y);
            hv.w = pack_h2(b.z, b.w);
            *reinterpret_cast<uint4*>(psm + QK_XHI(s) + sw_off(sr[i], sc)) = hv;
        }
        if (kc + 1 < DMODEL / 64) {
#pragma unroll
            for (int i = 0; i < 4; i++) {
                const float* src = X + (size_t)(row0 + sr[i]) * DMODEL
                                     + (k0 + 64) + sc * 8;
                xa[i] = *reinterpret_cast<const float4*>(src);
                xb[i] = *reinterpret_cast<const float4*>(src + 4);
            }
        }

        CP_WAIT0();
        __syncthreads();

        if (kc + 1 < DMODEL / 64) {
#pragma unroll
            for (int i = 0; i < 4; i++)
                CP_ASYNC16(sbase + QK_WHI(s ^ 1) + sw_off(sr[i], sc),
                           Whi + (size_t)(k0 + 64 + sr[i]) * DK + sc * 8);
            CP_COMMIT();
        }

        uint32_t aHi[4][4];
        {
            int arow = w * 16 + (qq & 1) * 8 + rr;
#pragma unroll
            for (int ss = 0; ss < 4; ss++) {
                uint32_t off = sw_off(arow, 2 * ss + (qq >> 1));
                LDSM_X4(aHi[ss][0], aHi[ss][1], aHi[ss][2], aHi[ss][3],
                        sbase + QK_XHI(s) + off);
            }
        }
        int brow_base = qq * 8 + rr;
#pragma unroll
        for (int j = 0; j < 8; j++) {
#pragma unroll
            for (int sp = 0; sp < 2; sp++) {
                int brow = 32 * sp + brow_base;
                uint32_t v0, v1, v2, v3;
                LDSM_X4_T(v0, v1, v2, v3, sbase + QK_WHI(s) + sw_off(brow, j));
                MMA16816(O[j], aHi[2 * sp],     v0, v1);
                MMA16816(O[j], aHi[2 * sp + 1], v2, v3);
            }
        }
    }

    const int row_a = row0 + w * 16 + g;
    const int row_b = row_a + 8;
    const float LOG2E_O8 = 0.125f * 1.4426950408889634f;
    const float sca = (which == 0) ? (mask[row_a] * LOG2E_O8) : 1.0f;
    const float scb = (which == 0) ? (mask[row_b] * LOG2E_O8) : 1.0f;
    __half* Y = (which == 0) ? g_qh : g_kh;
#pragma unroll
    for (int j = 0; j < 8; j++) {
        int col = 8 * j + 2 * t;
        float b0 = bias[col], b1 = bias[col + 1];
        *reinterpret_cast<uint32_t*>(&Y[(size_t)row_a * DK + col]) =
            pack_h2((O[j][0] + b0) * sca, (O[j][1] + b1) * sca);
        *reinterpret_cast<uint32_t*>(&Y[(size_t)row_b * DK + col]) =
            pack_h2((O[j][2] + b0) * scb, (O[j][3] + b1) * scb);
    }
}

// ============================================================================
// v projection: split-fp16 3-MMA. (R12, unchanged)
// ============================================================================
#define PJ_SMEM (8 * PJ_TILE)
#define OFF_XHI(s) ((s) * PJ_TILE)
#define OFF_XLO(s) (16384 + (s) * PJ_TILE)
#define OFF_WHI(s) (32768 + (s) * PJ_TILE)
#define OFF_WLO(s) (49152 + (s) * PJ_TILE)

__global__ __launch_bounds__(128) void proj_v_kernel(
    const float* __restrict__ Xv, const float* __restrict__ bv)
{
    extern __shared__ __align__(16) char psm[];
    const uint32_t sbase = cvta_smem(psm);

    const int tid  = threadIdx.x;
    const int lane = tid & 31;
    const int w    = tid >> 5;
    const int row0 = blockIdx.x * 64;
    const int g    = lane >> 2;
    const int t    = lane & 3;
    const int qq   = lane >> 3;
    const int rr   = lane & 7;

    const __half* Whi = g_Whi + 2 * DMODEL * DK;
    const __half* Wlo = g_Wlo + 2 * DMODEL * DK;

    const int sr[4] = { (tid) >> 3, (tid + 128) >> 3, (tid + 256) >> 3, (tid + 384) >> 3 };
    const int sc    = tid & 7;

    float O[8][4];
#pragma unroll
    for (int j = 0; j < 8; j++)
#pragma unroll
        for (int i = 0; i < 4; i++) O[j][i] = 0.f;

    float4 xa[4], xb[4];
#pragma unroll
    for (int i = 0; i < 4; i++) {
        const float* src = Xv + (size_t)(row0 + sr[i]) * DMODEL + sc * 8;
        xa[i] = *reinterpret_cast<const float4*>(src);
        xb[i] = *reinterpret_cast<const float4*>(src + 4);
    }
#pragma unroll
    for (int i = 0; i < 4; i++) {
        uint32_t so = sw_off(sr[i], sc);
        CP_ASYNC16(sbase + OFF_WHI(0) + so, Whi + (size_t)sr[i] * DK + sc * 8);
        CP_ASYNC16(sbase + OFF_WLO(0) + so, Wlo + (size_t)sr[i] * DK + sc * 8);
    }
    CP_COMMIT();

    for (int kc = 0; kc < DMODEL / 64; kc++) {
        const int s = kc & 1;
        const int k0 = kc * 64;

#pragma unroll
        for (int i = 0; i < 4; i++) {
            float4 a = xa[i], b = xb[i];
            __half h[8];
            h[0]=__float2half_rn(a.x); h[1]=__float2half_rn(a.y);
            h[2]=__float2half_rn(a.z); h[3]=__float2half_rn(a.w);
            h[4]=__float2half_rn(b.x); h[5]=__float2half_rn(b.y);
            h[6]=__float2half_rn(b.z); h[7]=__float2half_rn(b.w);
            uint4 hv, lv;
            hv.x = pack_h2(__half2float(h[0]), __half2float(h[1]));
            hv.y = pack_h2(__half2float(h[2]), __half2float(h[3]));
            hv.z = pack_h2(__half2float(h[4]), __half2float(h[5]));
            hv.w = pack_h2(__half2float(h[6]), __half2float(h[7]));
            lv.x = pack_h2(a.x - __half2float(h[0]), a.y - __half2float(h[1]));
            lv.y = pack_h2(a.z - __half2float(h[2]), a.w - __half2float(h[3]));
            lv.z = pack_h2(b.x - __half2float(h[4]), b.y - __half2float(h[5]));
            lv.w = pack_h2(b.z - __half2float(h[6]), b.w - __half2float(h[7]));
            uint32_t so = sw_off(sr[i], sc);
            *reinterpret_cast<uint4*>(psm + OFF_XHI(s) + so) = hv;
            *reinterpret_cast<uint4*>(psm + OFF_XLO(s) + so) = lv;
        }
        if (kc + 1 < DMODEL / 64) {
#pragma unroll
            for (int i = 0; i < 4; i++) {
                const float* src = Xv + (size_t)(row0 + sr[i]) * DMODEL
                                      + (k0 + 64) + sc * 8;
                xa[i] = *reinterpret_cast<const float4*>(src);
                xb[i] = *reinterpret_cast<const float4*>(src + 4);
            }
        }

        CP_WAIT0();
        __syncthreads();

        if (kc + 1 < DMODEL / 64) {
#pragma unroll
            for (int i = 0; i < 4; i++) {
                uint32_t so = sw_off(sr[i], sc);
                CP_ASYNC16(sbase + OFF_WHI(s ^ 1) + so,
                           Whi + (size_t)(k0 + 64 + sr[i]) * DK + sc * 8);
                CP_ASYNC16(sbase + OFF_WLO(s ^ 1) + so,
                           Wlo + (size_t)(k0 + 64 + sr[i]) * DK + sc * 8);
            }
            CP_COMMIT();
        }

        uint32_t aHi[4][4], aLo[4][4];
        {
            int arow = w * 16 + (qq & 1) * 8 + rr;
#pragma unroll
            for (int ss = 0; ss < 4; ss++) {
                uint32_t off = sw_off(arow, 2 * ss + (qq >> 1));
                LDSM_X4(aHi[ss][0], aHi[ss][1], aHi[ss][2], aHi[ss][3],
                        sbase + OFF_XHI(s) + off);
                LDSM_X4(aLo[ss][0], aLo[ss][1], aLo[ss][2], aLo[ss][3],
                        sbase + OFF_XLO(s) + off);
            }
        }
        int brow_base = qq * 8 + rr;
#pragma unroll
        for (int j = 0; j < 8; j++) {
#pragma unroll
            for (int sp = 0; sp < 2; sp++) {
                int brow = 32 * sp + brow_base;
                uint32_t v0, v1, v2, v3, u0, u1, u2, u3;
                LDSM_X4_T(v0, v1, v2, v3, sbase + OFF_WHI(s) + sw_off(brow, j));
                MMA16816(O[j], aHi[2 * sp],     v0, v1);
                MMA16816(O[j], aHi[2 * sp + 1], v2, v3);
                MMA16816(O[j], aLo[2 * sp],     v0, v1);
                MMA16816(O[j], aLo[2 * sp + 1], v2, v3);
                LDSM_X4_T(u0, u1, u2, u3, sbase + OFF_WLO(s) + sw_off(brow, j));
                MMA16816(O[j], aHi[2 * sp],     u0, u1);
                MMA16816(O[j], aHi[2 * sp + 1], u2, u3);
            }
        }
    }

    const int row_a = row0 + w * 16 + g;
    const int row_b = row_a + 8;
#pragma unroll
    for (int j = 0; j < 8; j++) {
        int col = 8 * j + 2 * t;
        float b0 = bv[col], b1 = bv[col + 1];
        *reinterpret_cast<uint32_t*>(&g_vh[(size_t)row_a * DK + col]) =
            pack_h2(O[j][0] + b0, O[j][1] + b1);
        *reinterpret_cast<uint32_t*>(&g_vh[(size_t)row_b * DK + col]) =
            pack_h2(O[j][2] + b0, O[j][3] + b1);
    }
}

// ============================================================================
// FlashAttention (R12 shape): BR=64, 4 warps, 4 CTAs/SM.
// S-MMA uses f16 accumulators -> 2x tensor rate on S, output directly packed
// for ex2.f16x2 (pack_h2 chain eliminated).
// ============================================================================
#define BR   64
#define BC   64
#define NKT_Z (SEQ / BC / ZSPLIT)      // 16 tiles per quarter

#define Q_BYTES     (BR * 128)
#define TILE_BYTES  (BC * 128)
#define STAGE_BYTES (2 * TILE_BYTES)               // K + V = 16KB
#define ATTN_SMEM   (Q_BYTES + 2 * STAGE_BYTES)    // 40960

__device__ __forceinline__ void prefetch_tile(char* stage, int b, int key0, int tid)
{
    const __half* srcs[2] = {g_kh, g_vh};
#pragma unroll
    for (int i = 0; i < 8; i++) {
        int idx = tid + i * 128;
        int arr = idx >> 9;
        int rem = idx & 511;
        int row = rem >> 3, c = rem & 7;
        const __half* g = srcs[arr] + ((size_t)b * SEQ + key0 + row) * DK + c * 8;
        uint32_t d = cvta_smem(stage + arr * TILE_BYTES) + sw_off(row, c);
        CP_ASYNC16(d, g);
    }
}

__global__ __launch_bounds__(128, 4) void attn_kernel()
{
    extern __shared__ char smem[];
    char* Qs = smem;
    char* St = smem + Q_BYTES;

    const int tid  = threadIdx.x;
    const int lane = tid & 31;
    const int w    = tid >> 5;
    const int b    = blockIdx.y;
    const int q0   = blockIdx.x * BR;
    const int z    = blockIdx.z;
    const int key_base = z * (SEQ / ZSPLIT);
    const int g    = lane >> 2;
    const int t    = lane & 3;
    const int qq   = lane >> 3;
    const int rr   = lane & 7;

    prefetch_tile(St, b, key_base, tid);
    CP_COMMIT();

    {
        const __half* qb = g_qh + ((size_t)b * SEQ + q0) * DK;
#pragma unroll
        for (int i = 0; i < 4; i++) {
            int idx = tid + i * 128;
            int row = idx >> 3, c = idx & 7;
            uint4 v = *reinterpret_cast<const uint4*>(qb + (size_t)row * DK + c * 8);
            *reinterpret_cast<uint4*>(Qs + sw_off(row, c)) = v;
        }
    }
    __syncthreads();

    uint32_t qA[4][4];
    {
        uint32_t qbase = cvta_smem(Qs);
        int row = w * 16 + (qq & 1) * 8 + rr;
#pragma unroll
        for (int s = 0; s < 4; s++) {
            uint32_t addr = qbase + sw_off(row, 2 * s + (qq >> 1));
            LDSM_X4(qA[s][0], qA[s][1], qA[s][2], qA[s][3], addr);
        }
    }

    float O[8][4];
#pragma unroll
    for (int j = 0; j < 8; j++)
#pragma unroll
        for (int i = 0; i < 4; i++) O[j][i] = 0.f;
    float OL[4] = {0.f, 0.f, 0.f, 0.f};
    const uint32_t ONE2 = 0x3C003C00u;

    for (int kt = 0; kt < NKT_Z; kt++) {
        const int s = kt & 1;
        char* stage = St + s * STAGE_BYTES;

        CP_WAIT0();
        __syncthreads();

        if (kt + 1 < NKT_Z) {
            prefetch_tile(St + (s ^ 1) * STAGE_BYTES, b,
                          key_base + (kt + 1) * BC, tid);
            CP_COMMIT();
        }

        const uint32_t kb  = cvta_smem(stage);
        const uint32_t vhb = kb + TILE_BYTES;

        // ---- S(base-2) via f16-acc MMA; d regs already packed for ex2 ----
        uint32_t aP[4][4];
#pragma unroll
        for (int j = 0; j < 8; j++) {
            uint32_t dP[2] = {0u, 0u};     // f16x2 accumulators (zero)
#pragma unroll
            for (int sp = 0; sp < 2; sp++) {
                int row = j * 8 + rr;
                uint32_t addr = kb + sw_off(row, 4 * sp + qq);
                uint32_t k0, k1, k2, k3;
                LDSM_X4(k0, k1, k2, k3, addr);
                MMA16816_F16(dP, qA[2 * sp],     k0, k1);
                MMA16816_F16(dP, qA[2 * sp + 1], k2, k3);
            }
            int sp2 = j >> 1, o = (j & 1) * 2;
            EX2_F16X2(aP[sp2][o],     dP[0]);
            EX2_F16X2(aP[sp2][o + 1], dP[1]);
        }

        // ---- L via ones-B MMA (f32 acc) ----
        MMA16816(OL, aP[0], ONE2, ONE2);
        MMA16816(OL, aP[1], ONE2, ONE2);
        MMA16816(OL, aP[2], ONE2, ONE2);
        MMA16816(OL, aP[3], ONE2, ONE2);

        // ---- O += P @ V (f32 acc) ----
#pragma unroll
        for (int j = 0; j < 8; j++) {
#pragma unroll
            for (int sp = 0; sp < 2; sp++) {
                int row = 32 * sp + qq * 8 + rr;
                uint32_t v0, v1, v2, v3;
                LDSM_X4_T(v0, v1, v2, v3, vhb + sw_off(row, j));
                MMA16816(O[j], aP[2 * sp],     v0, v1);
                MMA16816(O[j], aP[2 * sp + 1], v2, v3);
            }
        }
    }

    const size_t row_a = (size_t)b * SEQ + q0 + w * 16 + g;
    const size_t row_b = row_a + 8;
    float* Oz = g_Oacc[z];
    if (t == 0) {
        g_Lacc[z][row_a] = OL[0];
        g_Lacc[z][row_b] = OL[2];
    }
#pragma unroll
    for (int j = 0; j < 8; j++) {
        int col = 8 * j + 2 * t;
        *reinterpret_cast<float2*>(Oz + row_a * DK + col) =
            make_float2(O[j][0], O[j][1]);
        *reinterpret_cast<float2*>(Oz + row_b * DK + col) =
            make_float2(O[j][2], O[j][3]);
    }
}

// ============================================================================
// Normalize: out = sum_z O_z / sum_z L_z
// ============================================================================
__global__ __launch_bounds__(256) void normalize_kernel(float* __restrict__ out)
{
    int i = blockIdx.x * 256 + threadIdx.x;
    int row = i >> 4;
    float Lsum = 0.f;
#pragma unroll
    for (int z = 0; z < ZSPLIT; z++) Lsum += g_Lacc[z][row];
    float inv = 1.0f / Lsum;
    float4 r = make_float4(0.f, 0.f, 0.f, 0.f);
#pragma unroll
    for (int z = 0; z < ZSPLIT; z++) {
        float4 a = *reinterpret_cast<const float4*>(&g_Oacc[z][(size_t)i * 4]);
        r.x += a.x; r.y += a.y; r.z += a.z; r.w += a.w;
    }
    r.x *= inv; r.y *= inv; r.z *= inv; r.w *= inv;
    *reinterpret_cast<float4*>(out + (size_t)i * 4) = r;
}

// ============================================================================
// Stream/event infra (module load; streams/events only — no device memory)
// ============================================================================
static cudaStream_t g_s2   = nullptr;
static cudaEvent_t  g_fork = nullptr;
static cudaEvent_t  g_join = nullptr;
static const bool g_infra_init = []() {
    cudaStreamCreateWithFlags(&g_s2, cudaStreamNonBlocking);
    cudaEventCreateWithFlags(&g_fork, cudaEventDisableTiming);
    cudaEventCreateWithFlags(&g_join, cudaEventDisableTiming);
    return true;
}();

// ============================================================================
extern "C" void kernel_launch(void* const* d_in, const int* in_sizes, int n_in,
                              void* d_out, int out_size)
{
    const float* q  = (const float*)d_in[0];
    const float* k  = (const float*)d_in[1];
    const float* v  = (const float*)d_in[2];
    const float* m  = (const float*)d_in[3];
    const float* Wq = (const float*)d_in[4];
    const float* bq = (const float*)d_in[5];
    const float* Wk = (const float*)d_in[6];
    const float* bk = (const float*)d_in[7];
    const float* Wv = (const float*)d_in[8];
    const float* bv = (const float*)d_in[9];
    float* out = (float*)d_out;

    cudaFuncSetAttribute(proj_qk_kernel,
                         cudaFuncAttributeMaxDynamicSharedMemorySize, QK_SMEM);
    cudaFuncSetAttribute(proj_v_kernel,
                         cudaFuncAttributeMaxDynamicSharedMemorySize, PJ_SMEM);
    cudaFuncSetAttribute(attn_kernel,
                         cudaFuncAttributeMaxDynamicSharedMemorySize, ATTN_SMEM);

    dim3 wgrid(DMODEL * DK / 256, 3);
    wconv_kernel<<<wgrid, 256>>>(Wq, Wk, Wv);

    cudaEventRecord(g_fork, 0);
    cudaStreamWaitEvent(g_s2, g_fork, 0);

    proj_v_kernel<<<ROWS / 64, 128, PJ_SMEM, g_s2>>>(v, bv);
    cudaEventRecord(g_join, g_s2);

    dim3 qkgrid(ROWS / 64, 2);
    proj_qk_kernel<<<qkgrid, 128, QK_SMEM>>>(q, k, bq, bk, m);

    cudaStreamWaitEvent(0, g_join, 0);

    dim3 grid(SEQ / BR, BATCH, ZSPLIT);
    attn_kernel<<<grid, 128, ATTN_SMEM>>>();

    normalize_kernel<<<ROWS * DK / 4 / 256, 256>>>(out);
}

// round 15
// speedup vs baseline: 1.1263x; 1.0797x over previous
#include <cuda_runtime.h>
#include <cuda_fp16.h>
#include <cstdint>

// ============================================================================
// Problem constants
// ============================================================================
#define BATCH   4
#define SEQ     4096
#define DMODEL  1024
#define DK      64
#define ROWS    (BATCH * SEQ)        // 16384

// Projected tensors. q folded with mask*0.125*log2(e) -> logits in base-2.
__device__ __align__(16) __half g_qh [ROWS * DK];
__device__ __align__(16) __half g_kh [ROWS * DK];
__device__ __align__(16) __half g_vh [ROWS * DK];

// Pre-converted weights (fp16), 3 projections flat
__device__ __align__(16) __half g_Whi[3 * DMODEL * DK];

// split-K attention scratch: 4 quarters write disjoint buffers (deterministic)
#define ZSPLIT 4
__device__ float g_Oacc[ZSPLIT][ROWS * DK];
__device__ float g_Lacc[ZSPLIT][ROWS];

// ============================================================================
// small helpers
// ============================================================================
__device__ __forceinline__ uint32_t cvta_smem(const void* p) {
    return (uint32_t)__cvta_generic_to_shared(p);
}

#define LDSM_X4(r0, r1, r2, r3, addr) \
    asm volatile("ldmatrix.sync.aligned.m8n8.x4.shared.b16 {%0,%1,%2,%3}, [%4];" \
        : "=r"(r0), "=r"(r1), "=r"(r2), "=r"(r3) : "r"(addr))

#define LDSM_X4_T(r0, r1, r2, r3, addr) \
    asm volatile("ldmatrix.sync.aligned.m8n8.x4.trans.shared.b16 {%0,%1,%2,%3}, [%4];" \
        : "=r"(r0), "=r"(r1), "=r"(r2), "=r"(r3) : "r"(addr))

#define MMA16816(d, a, b0, b1) \
    asm volatile("mma.sync.aligned.m16n8k16.row.col.f32.f16.f16.f32 " \
        "{%0,%1,%2,%3}, {%4,%5,%6,%7}, {%8,%9}, {%0,%1,%2,%3};" \
        : "+f"((d)[0]), "+f"((d)[1]), "+f"((d)[2]), "+f"((d)[3]) \
        : "r"((a)[0]), "r"((a)[1]), "r"((a)[2]), "r"((a)[3]), "r"(b0), "r"(b1))

// f16-accumulate MMA
#define MMA16816_F16(d, a, b0, b1) \
    asm volatile("mma.sync.aligned.m16n8k16.row.col.f16.f16.f16.f16 " \
        "{%0,%1}, {%2,%3,%4,%5}, {%6,%7}, {%0,%1};" \
        : "+r"((d)[0]), "+r"((d)[1]) \
        : "r"((a)[0]), "r"((a)[1]), "r"((a)[2]), "r"((a)[3]), "r"(b0), "r"(b1))

#define CP_ASYNC16(dst, src) \
    asm volatile("cp.async.cg.shared.global [%0], [%1], 16;" \
        :: "r"(dst), "l"(src) : "memory")
#define CP_COMMIT()  asm volatile("cp.async.commit_group;" ::: "memory")
#define CP_WAIT0()   asm volatile("cp.async.wait_group 0;" ::: "memory")

#define EX2_F16X2(dst, src) \
    asm volatile("ex2.approx.f16x2 %0, %1;" : "=r"(dst) : "r"(src))

__device__ __forceinline__ uint32_t pack_h2(float a, float b) {
    __half2 h = __floats2half2_rn(a, b);
    return *reinterpret_cast<uint32_t*>(&h);
}

// smem swizzle: row-major fp16 tiles, row = 128B = 8 chunks of 16B.
__device__ __forceinline__ uint32_t sw_off(int row, int chunk) {
    return (uint32_t)(row * 128 + ((chunk ^ (row & 7)) << 4));
}

// ============================================================================
// Weight pre-conversion: fp32 -> fp16, once (hi only; all GEMMs plain fp16).
// ============================================================================
__global__ __launch_bounds__(256) void wconv_kernel(
    const float* __restrict__ Wq, const float* __restrict__ Wk,
    const float* __restrict__ Wv)
{
    int i = blockIdx.x * 256 + threadIdx.x;
    int which = blockIdx.y;
    const float* W = (which == 0) ? Wq : (which == 1) ? Wk : Wv;
    g_Whi[which * DMODEL * DK + i] = __float2half_rn(W[i]);
}

// ============================================================================
// Unified projection: plain fp16 GEMM for q, k, v (which = blockIdx.y).
//   q folds mask*0.125*log2(e). 32KB smem -> 5+ CTAs/SM; 768 CTAs stream
//   the full 192MB fp32 X read at high DRAM utilization.
// ============================================================================
#define PJ_TILE 8192
#define QK_SMEM (4 * PJ_TILE)             // Xhi2 + Whi2 = 32KB
#define QK_XHI(s) ((s) * PJ_TILE)
#define QK_WHI(s) (16384 + (s) * PJ_TILE)

__global__ __launch_bounds__(128) void proj_all_kernel(
    const float* __restrict__ Xq, const float* __restrict__ Xk,
    const float* __restrict__ Xv,
    const float* __restrict__ bq, const float* __restrict__ bk,
    const float* __restrict__ bv,
    const float* __restrict__ mask)
{
    extern __shared__ __align__(16) char psm[];
    const uint32_t sbase = cvta_smem(psm);

    const int tid   = threadIdx.x;
    const int lane  = tid & 31;
    const int w     = tid >> 5;
    const int which = blockIdx.y;         // 0=q, 1=k, 2=v
    const int row0  = blockIdx.x * 64;
    const int g     = lane >> 2;
    const int t     = lane & 3;
    const int qq    = lane >> 3;
    const int rr    = lane & 7;

    const float* X    = (which == 0) ? Xq : (which == 1) ? Xk : Xv;
    const float* bias = (which == 0) ? bq : (which == 1) ? bk : bv;
    const __half* Whi = g_Whi + which * DMODEL * DK;

    const int sr[4] = { (tid) >> 3, (tid + 128) >> 3, (tid + 256) >> 3, (tid + 384) >> 3 };
    const int sc    = tid & 7;

    float O[8][4];
#pragma unroll
    for (int j = 0; j < 8; j++)
#pragma unroll
        for (int i = 0; i < 4; i++) O[j][i] = 0.f;

    // prologue: X(0) regs + W(0) cp.async into stage 0
    float4 xa[4], xb[4];
#pragma unroll
    for (int i = 0; i < 4; i++) {
        const float* src = X + (size_t)(row0 + sr[i]) * DMODEL + sc * 8;
        xa[i] = *reinterpret_cast<const float4*>(src);
        xb[i] = *reinterpret_cast<const float4*>(src + 4);
    }
#pragma unroll
    for (int i = 0; i < 4; i++)
        CP_ASYNC16(sbase + QK_WHI(0) + sw_off(sr[i], sc),
                   Whi + (size_t)sr[i] * DK + sc * 8);
    CP_COMMIT();

    for (int kc = 0; kc < DMODEL / 64; kc++) {
        const int s = kc & 1;
        const int k0 = kc * 64;

#pragma unroll
        for (int i = 0; i < 4; i++) {
            float4 a = xa[i], b = xb[i];
            uint4 hv;
            hv.x = pack_h2(a.x, a.y);
            hv.y = pack_h2(a.z, a.w);
            hv.z = pack_h2(b.x, b.y);
            hv.w = pack_h2(b.z, b.w);
            *reinterpret_cast<uint4*>(psm + QK_XHI(s) + sw_off(sr[i], sc)) = hv;
        }
        if (kc + 1 < DMODEL / 64) {
#pragma unroll
            for (int i = 0; i < 4; i++) {
                const float* src = X + (size_t)(row0 + sr[i]) * DMODEL
                                     + (k0 + 64) + sc * 8;
                xa[i] = *reinterpret_cast<const float4*>(src);
                xb[i] = *reinterpret_cast<const float4*>(src + 4);
            }
        }

        CP_WAIT0();
        __syncthreads();

        if (kc + 1 < DMODEL / 64) {
#pragma unroll
            for (int i = 0; i < 4; i++)
                CP_ASYNC16(sbase + QK_WHI(s ^ 1) + sw_off(sr[i], sc),
                           Whi + (size_t)(k0 + 64 + sr[i]) * DK + sc * 8);
            CP_COMMIT();
        }

        uint32_t aHi[4][4];
        {
            int arow = w * 16 + (qq & 1) * 8 + rr;
#pragma unroll
            for (int ss = 0; ss < 4; ss++) {
                uint32_t off = sw_off(arow, 2 * ss + (qq >> 1));
                LDSM_X4(aHi[ss][0], aHi[ss][1], aHi[ss][2], aHi[ss][3],
                        sbase + QK_XHI(s) + off);
            }
        }
        int brow_base = qq * 8 + rr;
#pragma unroll
        for (int j = 0; j < 8; j++) {
#pragma unroll
            for (int sp = 0; sp < 2; sp++) {
                int brow = 32 * sp + brow_base;
                uint32_t v0, v1, v2, v3;
                LDSM_X4_T(v0, v1, v2, v3, sbase + QK_WHI(s) + sw_off(brow, j));
                MMA16816(O[j], aHi[2 * sp],     v0, v1);
                MMA16816(O[j], aHi[2 * sp + 1], v2, v3);
            }
        }
    }

    const int row_a = row0 + w * 16 + g;
    const int row_b = row_a + 8;
    // q rows get mask/8 * log2(e); k and v get 1.0
    const float LOG2E_O8 = 0.125f * 1.4426950408889634f;
    const float sca = (which == 0) ? (mask[row_a] * LOG2E_O8) : 1.0f;
    const float scb = (which == 0) ? (mask[row_b] * LOG2E_O8) : 1.0f;
    __half* Y = (which == 0) ? g_qh : (which == 1) ? g_kh : g_vh;
#pragma unroll
    for (int j = 0; j < 8; j++) {
        int col = 8 * j + 2 * t;
        float b0 = bias[col], b1 = bias[col + 1];
        *reinterpret_cast<uint32_t*>(&Y[(size_t)row_a * DK + col]) =
            pack_h2((O[j][0] + b0) * sca, (O[j][1] + b1) * sca);
        *reinterpret_cast<uint32_t*>(&Y[(size_t)row_b * DK + col]) =
            pack_h2((O[j][2] + b0) * scb, (O[j][3] + b1) * scb);
    }
}

// ============================================================================
// FlashAttention (R14, unchanged): BR=64, f16-acc S, ex2.f16x2, ones-B L.
// ============================================================================
#define BR   64
#define BC   64
#define NKT_Z (SEQ / BC / ZSPLIT)      // 16 tiles per quarter

#define Q_BYTES     (BR * 128)
#define TILE_BYTES  (BC * 128)
#define STAGE_BYTES (2 * TILE_BYTES)               // K + V = 16KB
#define ATTN_SMEM   (Q_BYTES + 2 * STAGE_BYTES)    // 40960

__device__ __forceinline__ void prefetch_tile(char* stage, int b, int key0, int tid)
{
    const __half* srcs[2] = {g_kh, g_vh};
#pragma unroll
    for (int i = 0; i < 8; i++) {
        int idx = tid + i * 128;
        int arr = idx >> 9;
        int rem = idx & 511;
        int row = rem >> 3, c = rem & 7;
        const __half* g = srcs[arr] + ((size_t)b * SEQ + key0 + row) * DK + c * 8;
        uint32_t d = cvta_smem(stage + arr * TILE_BYTES) + sw_off(row, c);
        CP_ASYNC16(d, g);
    }
}

__global__ __launch_bounds__(128, 4) void attn_kernel()
{
    extern __shared__ char smem[];
    char* Qs = smem;
    char* St = smem + Q_BYTES;

    const int tid  = threadIdx.x;
    const int lane = tid & 31;
    const int w    = tid >> 5;
    const int b    = blockIdx.y;
    const int q0   = blockIdx.x * BR;
    const int z    = blockIdx.z;
    const int key_base = z * (SEQ / ZSPLIT);
    const int g    = lane >> 2;
    const int t    = lane & 3;
    const int qq   = lane >> 3;
    const int rr   = lane & 7;

    prefetch_tile(St, b, key_base, tid);
    CP_COMMIT();

    {
        const __half* qb = g_qh + ((size_t)b * SEQ + q0) * DK;
#pragma unroll
        for (int i = 0; i < 4; i++) {
            int idx = tid + i * 128;
            int row = idx >> 3, c = idx & 7;
            uint4 v = *reinterpret_cast<const uint4*>(qb + (size_t)row * DK + c * 8);
            *reinterpret_cast<uint4*>(Qs + sw_off(row, c)) = v;
        }
    }
    __syncthreads();

    uint32_t qA[4][4];
    {
        uint32_t qbase = cvta_smem(Qs);
        int row = w * 16 + (qq & 1) * 8 + rr;
#pragma unroll
        for (int s = 0; s < 4; s++) {
            uint32_t addr = qbase + sw_off(row, 2 * s + (qq >> 1));
            LDSM_X4(qA[s][0], qA[s][1], qA[s][2], qA[s][3], addr);
        }
    }

    float O[8][4];
#pragma unroll
    for (int j = 0; j < 8; j++)
#pragma unroll
        for (int i = 0; i < 4; i++) O[j][i] = 0.f;
    float OL[4] = {0.f, 0.f, 0.f, 0.f};
    const uint32_t ONE2 = 0x3C003C00u;

    for (int kt = 0; kt < NKT_Z; kt++) {
        const int s = kt & 1;
        char* stage = St + s * STAGE_BYTES;

        CP_WAIT0();
        __syncthreads();

        if (kt + 1 < NKT_Z) {
            prefetch_tile(St + (s ^ 1) * STAGE_BYTES, b,
                          key_base + (kt + 1) * BC, tid);
            CP_COMMIT();
        }

        const uint32_t kb  = cvta_smem(stage);
        const uint32_t vhb = kb + TILE_BYTES;

        uint32_t aP[4][4];
#pragma unroll
        for (int j = 0; j < 8; j++) {
            uint32_t dP[2] = {0u, 0u};
#pragma unroll
            for (int sp = 0; sp < 2; sp++) {
                int row = j * 8 + rr;
                uint32_t addr = kb + sw_off(row, 4 * sp + qq);
                uint32_t k0, k1, k2, k3;
                LDSM_X4(k0, k1, k2, k3, addr);
                MMA16816_F16(dP, qA[2 * sp],     k0, k1);
                MMA16816_F16(dP, qA[2 * sp + 1], k2, k3);
            }
            int sp2 = j >> 1, o = (j & 1) * 2;
            EX2_F16X2(aP[sp2][o],     dP[0]);
            EX2_F16X2(aP[sp2][o + 1], dP[1]);
        }

        MMA16816(OL, aP[0], ONE2, ONE2);
        MMA16816(OL, aP[1], ONE2, ONE2);
        MMA16816(OL, aP[2], ONE2, ONE2);
        MMA16816(OL, aP[3], ONE2, ONE2);

#pragma unroll
        for (int j = 0; j < 8; j++) {
#pragma unroll
            for (int sp = 0; sp < 2; sp++) {
                int row = 32 * sp + qq * 8 + rr;
                uint32_t v0, v1, v2, v3;
                LDSM_X4_T(v0, v1, v2, v3, vhb + sw_off(row, j));
                MMA16816(O[j], aP[2 * sp],     v0, v1);
                MMA16816(O[j], aP[2 * sp + 1], v2, v3);
            }
        }
    }

    const size_t row_a = (size_t)b * SEQ + q0 + w * 16 + g;
    const size_t row_b = row_a + 8;
    float* Oz = g_Oacc[z];
    if (t == 0) {
        g_Lacc[z][row_a] = OL[0];
        g_Lacc[z][row_b] = OL[2];
    }
#pragma unroll
    for (int j = 0; j < 8; j++) {
        int col = 8 * j + 2 * t;
        *reinterpret_cast<float2*>(Oz + row_a * DK + col) =
            make_float2(O[j][0], O[j][1]);
        *reinterpret_cast<float2*>(Oz + row_b * DK + col) =
            make_float2(O[j][2], O[j][3]);
    }
}

// ============================================================================
// Normalize: out = sum_z O_z / sum_z L_z
// ============================================================================
__global__ __launch_bounds__(256) void normalize_kernel(float* __restrict__ out)
{
    int i = blockIdx.x * 256 + threadIdx.x;
    int row = i >> 4;
    float Lsum = 0.f;
#pragma unroll
    for (int z = 0; z < ZSPLIT; z++) Lsum += g_Lacc[z][row];
    float inv = 1.0f / Lsum;
    float4 r = make_float4(0.f, 0.f, 0.f, 0.f);
#pragma unroll
    for (int z = 0; z < ZSPLIT; z++) {
        float4 a = *reinterpret_cast<const float4*>(&g_Oacc[z][(size_t)i * 4]);
        r.x += a.x; r.y += a.y; r.z += a.z; r.w += a.w;
    }
    r.x *= inv; r.y *= inv; r.z *= inv; r.w *= inv;
    *reinterpret_cast<float4*>(out + (size_t)i * 4) = r;
}

// ============================================================================
extern "C" void kernel_launch(void* const* d_in, const int* in_sizes, int n_in,
                              void* d_out, int out_size)
{
    const float* q  = (const float*)d_in[0];
    const float* k  = (const float*)d_in[1];
    const float* v  = (const float*)d_in[2];
    const float* m  = (const float*)d_in[3];
    const float* Wq = (const float*)d_in[4];
    const float* bq = (const float*)d_in[5];
    const float* Wk = (const float*)d_in[6];
    const float* bk = (const float*)d_in[7];
    const float* Wv = (const float*)d_in[8];
    const float* bv = (const float*)d_in[9];
    float* out = (float*)d_out;

    cudaFuncSetAttribute(proj_all_kernel,
                         cudaFuncAttributeMaxDynamicSharedMemorySize, QK_SMEM);
    cudaFuncSetAttribute(attn_kernel,
                         cudaFuncAttributeMaxDynamicSharedMemorySize, ATTN_SMEM);

    dim3 wgrid(DMODEL * DK / 256, 3);
    wconv_kernel<<<wgrid, 256>>>(Wq, Wk, Wv);

    dim3 pgrid(ROWS / 64, 3);
    proj_all_kernel<<<pgrid, 128, QK_SMEM>>>(q, k, v, bq, bk, bv, m);

    dim3 grid(SEQ / BR, BATCH, ZSPLIT);
    attn_kernel<<<grid, 128, ATTN_SMEM>>>();

    normalize_kernel<<<ROWS * DK / 4 / 256, 256>>>(out);
}

// round 16
// speedup vs baseline: 1.1323x; 1.0053x over previous
#include <cuda_runtime.h>
#include <cuda_fp16.h>
#include <cstdint>

// ============================================================================
// Problem constants
// ============================================================================
#define BATCH   4
#define SEQ     4096
#define DMODEL  1024
#define DK      64
#define ROWS    (BATCH * SEQ)        // 16384

// Projected tensors. q folded with mask*0.125*log2(e) -> logits in base-2.
__device__ __align__(16) __half g_qh [ROWS * DK];
__device__ __align__(16) __half g_kh [ROWS * DK];
__device__ __align__(16) __half g_vh [ROWS * DK];

// Pre-converted weights (fp16), 3 projections flat
__device__ __align__(16) __half g_Whi[3 * DMODEL * DK];

// split-K attention scratch: partial O in f16 (error budgeted), L in f32
#define ZSPLIT 4
__device__ __align__(16) __half g_Oacc[ZSPLIT][ROWS * DK];
__device__ float g_Lacc[ZSPLIT][ROWS];

// ============================================================================
// small helpers
// ============================================================================
__device__ __forceinline__ uint32_t cvta_smem(const void* p) {
    return (uint32_t)__cvta_generic_to_shared(p);
}

#define LDSM_X4(r0, r1, r2, r3, addr) \
    asm volatile("ldmatrix.sync.aligned.m8n8.x4.shared.b16 {%0,%1,%2,%3}, [%4];" \
        : "=r"(r0), "=r"(r1), "=r"(r2), "=r"(r3) : "r"(addr))

#define LDSM_X4_T(r0, r1, r2, r3, addr) \
    asm volatile("ldmatrix.sync.aligned.m8n8.x4.trans.shared.b16 {%0,%1,%2,%3}, [%4];" \
        : "=r"(r0), "=r"(r1), "=r"(r2), "=r"(r3) : "r"(addr))

#define MMA16816(d, a, b0, b1) \
    asm volatile("mma.sync.aligned.m16n8k16.row.col.f32.f16.f16.f32 " \
        "{%0,%1,%2,%3}, {%4,%5,%6,%7}, {%8,%9}, {%0,%1,%2,%3};" \
        : "+f"((d)[0]), "+f"((d)[1]), "+f"((d)[2]), "+f"((d)[3]) \
        : "r"((a)[0]), "r"((a)[1]), "r"((a)[2]), "r"((a)[3]), "r"(b0), "r"(b1))

// f16-accumulate MMA
#define MMA16816_F16(d, a, b0, b1) \
    asm volatile("mma.sync.aligned.m16n8k16.row.col.f16.f16.f16.f16 " \
        "{%0,%1}, {%2,%3,%4,%5}, {%6,%7}, {%0,%1};" \
        : "+r"((d)[0]), "+r"((d)[1]) \
        : "r"((a)[0]), "r"((a)[1]), "r"((a)[2]), "r"((a)[3]), "r"(b0), "r"(b1))

#define CP_ASYNC16(dst, src) \
    asm volatile("cp.async.cg.shared.global [%0], [%1], 16;" \
        :: "r"(dst), "l"(src) : "memory")
#define CP_COMMIT()  asm volatile("cp.async.commit_group;" ::: "memory")
#define CP_WAIT0()   asm volatile("cp.async.wait_group 0;" ::: "memory")

#define EX2_F16X2(dst, src) \
    asm volatile("ex2.approx.f16x2 %0, %1;" : "=r"(dst) : "r"(src))

__device__ __forceinline__ uint32_t pack_h2(float a, float b) {
    __half2 h = __floats2half2_rn(a, b);
    return *reinterpret_cast<uint32_t*>(&h);
}

// smem swizzle: row-major fp16 tiles, row = 128B = 8 chunks of 16B.
__device__ __forceinline__ uint32_t sw_off(int row, int chunk) {
    return (uint32_t)(row * 128 + ((chunk ^ (row & 7)) << 4));
}

// ============================================================================
// Weight pre-conversion: fp32 -> fp16, once.
// ============================================================================
__global__ __launch_bounds__(256) void wconv_kernel(
    const float* __restrict__ Wq, const float* __restrict__ Wk,
    const float* __restrict__ Wv)
{
    int i = blockIdx.x * 256 + threadIdx.x;
    int which = blockIdx.y;
    const float* W = (which == 0) ? Wq : (which == 1) ? Wk : Wv;
    g_Whi[which * DMODEL * DK + i] = __float2half_rn(W[i]);
}

// ============================================================================
// Unified projection: plain fp16 GEMM for q, k, v (R15, unchanged).
// ============================================================================
#define PJ_TILE 8192
#define QK_SMEM (4 * PJ_TILE)             // Xhi2 + Whi2 = 32KB
#define QK_XHI(s) ((s) * PJ_TILE)
#define QK_WHI(s) (16384 + (s) * PJ_TILE)

__global__ __launch_bounds__(128) void proj_all_kernel(
    const float* __restrict__ Xq, const float* __restrict__ Xk,
    const float* __restrict__ Xv,
    const float* __restrict__ bq, const float* __restrict__ bk,
    const float* __restrict__ bv,
    const float* __restrict__ mask)
{
    extern __shared__ __align__(16) char psm[];
    const uint32_t sbase = cvta_smem(psm);

    const int tid   = threadIdx.x;
    const int lane  = tid & 31;
    const int w     = tid >> 5;
    const int which = blockIdx.y;         // 0=q, 1=k, 2=v
    const int row0  = blockIdx.x * 64;
    const int g     = lane >> 2;
    const int t     = lane & 3;
    const int qq    = lane >> 3;
    const int rr    = lane & 7;

    const float* X    = (which == 0) ? Xq : (which == 1) ? Xk : Xv;
    const float* bias = (which == 0) ? bq : (which == 1) ? bk : bv;
    const __half* Whi = g_Whi + which * DMODEL * DK;

    const int sr[4] = { (tid) >> 3, (tid + 128) >> 3, (tid + 256) >> 3, (tid + 384) >> 3 };
    const int sc    = tid & 7;

    float O[8][4];
#pragma unroll
    for (int j = 0; j < 8; j++)
#pragma unroll
        for (int i = 0; i < 4; i++) O[j][i] = 0.f;

    float4 xa[4], xb[4];
#pragma unroll
    for (int i = 0; i < 4; i++) {
        const float* src = X + (size_t)(row0 + sr[i]) * DMODEL + sc * 8;
        xa[i] = *reinterpret_cast<const float4*>(src);
        xb[i] = *reinterpret_cast<const float4*>(src + 4);
    }
#pragma unroll
    for (int i = 0; i < 4; i++)
        CP_ASYNC16(sbase + QK_WHI(0) + sw_off(sr[i], sc),
                   Whi + (size_t)sr[i] * DK + sc * 8);
    CP_COMMIT();

    for (int kc = 0; kc < DMODEL / 64; kc++) {
        const int s = kc & 1;
        const int k0 = kc * 64;

#pragma unroll
        for (int i = 0; i < 4; i++) {
            float4 a = xa[i], b = xb[i];
            uint4 hv;
            hv.x = pack_h2(a.x, a.y);
            hv.y = pack_h2(a.z, a.w);
            hv.z = pack_h2(b.x, b.y);
            hv.w = pack_h2(b.z, b.w);
            *reinterpret_cast<uint4*>(psm + QK_XHI(s) + sw_off(sr[i], sc)) = hv;
        }
        if (kc + 1 < DMODEL / 64) {
#pragma unroll
            for (int i = 0; i < 4; i++) {
                const float* src = X + (size_t)(row0 + sr[i]) * DMODEL
                                     + (k0 + 64) + sc * 8;
                xa[i] = *reinterpret_cast<const float4*>(src);
                xb[i] = *reinterpret_cast<const float4*>(src + 4);
            }
        }

        CP_WAIT0();
        __syncthreads();

        if (kc + 1 < DMODEL / 64) {
#pragma unroll
            for (int i = 0; i < 4; i++)
                CP_ASYNC16(sbase + QK_WHI(s ^ 1) + sw_off(sr[i], sc),
                           Whi + (size_t)(k0 + 64 + sr[i]) * DK + sc * 8);
            CP_COMMIT();
        }

        uint32_t aHi[4][4];
        {
            int arow = w * 16 + (qq & 1) * 8 + rr;
#pragma unroll
            for (int ss = 0; ss < 4; ss++) {
                uint32_t off = sw_off(arow, 2 * ss + (qq >> 1));
                LDSM_X4(aHi[ss][0], aHi[ss][1], aHi[ss][2], aHi[ss][3],
                        sbase + QK_XHI(s) + off);
            }
        }
        int brow_base = qq * 8 + rr;
#pragma unroll
        for (int j = 0; j < 8; j++) {
#pragma unroll
            for (int sp = 0; sp < 2; sp++) {
                int brow = 32 * sp + brow_base;
                uint32_t v0, v1, v2, v3;
                LDSM_X4_T(v0, v1, v2, v3, sbase + QK_WHI(s) + sw_off(brow, j));
                MMA16816(O[j], aHi[2 * sp],     v0, v1);
                MMA16816(O[j], aHi[2 * sp + 1], v2, v3);
            }
        }
    }

    const int row_a = row0 + w * 16 + g;
    const int row_b = row_a + 8;
    const float LOG2E_O8 = 0.125f * 1.4426950408889634f;
    const float sca = (which == 0) ? (mask[row_a] * LOG2E_O8) : 1.0f;
    const float scb = (which == 0) ? (mask[row_b] * LOG2E_O8) : 1.0f;
    __half* Y = (which == 0) ? g_qh : (which == 1) ? g_kh : g_vh;
#pragma unroll
    for (int j = 0; j < 8; j++) {
        int col = 8 * j + 2 * t;
        float b0 = bias[col], b1 = bias[col + 1];
        *reinterpret_cast<uint32_t*>(&Y[(size_t)row_a * DK + col]) =
            pack_h2((O[j][0] + b0) * sca, (O[j][1] + b1) * sca);
        *reinterpret_cast<uint32_t*>(&Y[(size_t)row_b * DK + col]) =
            pack_h2((O[j][2] + b0) * scb, (O[j][3] + b1) * scb);
    }
}

// ============================================================================
// FlashAttention (R14 core): BR=64, f16-acc S, ex2.f16x2, ones-B L.
// Epilogue now emits f16 partials (halved scratch traffic).
// ============================================================================
#define BR   64
#define BC   64
#define NKT_Z (SEQ / BC / ZSPLIT)      // 16 tiles per quarter

#define Q_BYTES     (BR * 128)
#define TILE_BYTES  (BC * 128)
#define STAGE_BYTES (2 * TILE_BYTES)               // K + V = 16KB
#define ATTN_SMEM   (Q_BYTES + 2 * STAGE_BYTES)    // 40960

__device__ __forceinline__ void prefetch_tile(char* stage, int b, int key0, int tid)
{
    const __half* srcs[2] = {g_kh, g_vh};
#pragma unroll
    for (int i = 0; i < 8; i++) {
        int idx = tid + i * 128;
        int arr = idx >> 9;
        int rem = idx & 511;
        int row = rem >> 3, c = rem & 7;
        const __half* g = srcs[arr] + ((size_t)b * SEQ + key0 + row) * DK + c * 8;
        uint32_t d = cvta_smem(stage + arr * TILE_BYTES) + sw_off(row, c);
        CP_ASYNC16(d, g);
    }
}

__global__ __launch_bounds__(128, 4) void attn_kernel()
{
    extern __shared__ char smem[];
    char* Qs = smem;
    char* St = smem + Q_BYTES;

    const int tid  = threadIdx.x;
    const int lane = tid & 31;
    const int w    = tid >> 5;
    const int b    = blockIdx.y;
    const int q0   = blockIdx.x * BR;
    const int z    = blockIdx.z;
    const int key_base = z * (SEQ / ZSPLIT);
    const int g    = lane >> 2;
    const int t    = lane & 3;
    const int qq   = lane >> 3;
    const int rr   = lane & 7;

    prefetch_tile(St, b, key_base, tid);
    CP_COMMIT();

    {
        const __half* qb = g_qh + ((size_t)b * SEQ + q0) * DK;
#pragma unroll
        for (int i = 0; i < 4; i++) {
            int idx = tid + i * 128;
            int row = idx >> 3, c = idx & 7;
            uint4 v = *reinterpret_cast<const uint4*>(qb + (size_t)row * DK + c * 8);
            *reinterpret_cast<uint4*>(Qs + sw_off(row, c)) = v;
        }
    }
    __syncthreads();

    uint32_t qA[4][4];
    {
        uint32_t qbase = cvta_smem(Qs);
        int row = w * 16 + (qq & 1) * 8 + rr;
#pragma unroll
        for (int s = 0; s < 4; s++) {
            uint32_t addr = qbase + sw_off(row, 2 * s + (qq >> 1));
            LDSM_X4(qA[s][0], qA[s][1], qA[s][2], qA[s][3], addr);
        }
    }

    float O[8][4];
#pragma unroll
    for (int j = 0; j < 8; j++)
#pragma unroll
        for (int i = 0; i < 4; i++) O[j][i] = 0.f;
    float OL[4] = {0.f, 0.f, 0.f, 0.f};
    const uint32_t ONE2 = 0x3C003C00u;

    for (int kt = 0; kt < NKT_Z; kt++) {
        const int s = kt & 1;
        char* stage = St + s * STAGE_BYTES;

        CP_WAIT0();
        __syncthreads();

        if (kt + 1 < NKT_Z) {
            prefetch_tile(St + (s ^ 1) * STAGE_BYTES, b,
                          key_base + (kt + 1) * BC, tid);
            CP_COMMIT();
        }

        const uint32_t kb  = cvta_smem(stage);
        const uint32_t vhb = kb + TILE_BYTES;

        uint32_t aP[4][4];
#pragma unroll
        for (int j = 0; j < 8; j++) {
            uint32_t dP[2] = {0u, 0u};
#pragma unroll
            for (int sp = 0; sp < 2; sp++) {
                int row = j * 8 + rr;
                uint32_t addr = kb + sw_off(row, 4 * sp + qq);
                uint32_t k0, k1, k2, k3;
                LDSM_X4(k0, k1, k2, k3, addr);
                MMA16816_F16(dP, qA[2 * sp],     k0, k1);
                MMA16816_F16(dP, qA[2 * sp + 1], k2, k3);
            }
            int sp2 = j >> 1, o = (j & 1) * 2;
            EX2_F16X2(aP[sp2][o],     dP[0]);
            EX2_F16X2(aP[sp2][o + 1], dP[1]);
        }

        MMA16816(OL, aP[0], ONE2, ONE2);
        MMA16816(OL, aP[1], ONE2, ONE2);
        MMA16816(OL, aP[2], ONE2, ONE2);
        MMA16816(OL, aP[3], ONE2, ONE2);

#pragma unroll
        for (int j = 0; j < 8; j++) {
#pragma unroll
            for (int sp = 0; sp < 2; sp++) {
                int row = 32 * sp + qq * 8 + rr;
                uint32_t v0, v1, v2, v3;
                LDSM_X4_T(v0, v1, v2, v3, vhb + sw_off(row, j));
                MMA16816(O[j], aP[2 * sp],     v0, v1);
                MMA16816(O[j], aP[2 * sp + 1], v2, v3);
            }
        }
    }

    // ---- epilogue: f16 partial O, f32 L ----
    const size_t row_a = (size_t)b * SEQ + q0 + w * 16 + g;
    const size_t row_b = row_a + 8;
    __half* Oz = g_Oacc[z];
    if (t == 0) {
        g_Lacc[z][row_a] = OL[0];
        g_Lacc[z][row_b] = OL[2];
    }
#pragma unroll
    for (int j = 0; j < 8; j++) {
        int col = 8 * j + 2 * t;
        *reinterpret_cast<uint32_t*>(&Oz[row_a * DK + col]) =
            pack_h2(O[j][0], O[j][1]);
        *reinterpret_cast<uint32_t*>(&Oz[row_b * DK + col]) =
            pack_h2(O[j][2], O[j][3]);
    }
}

// ============================================================================
// Normalize: out = sum_z O_z / sum_z L_z.  8 outputs/thread, 4 independent
// 16B loads in flight per z-pass (MLP-friendly).
// ============================================================================
__global__ __launch_bounds__(256) void normalize_kernel(float* __restrict__ out)
{
    int idx = blockIdx.x * 256 + threadIdx.x;    // unit = 8 elements
    int row = idx >> 3;
    float Lsum = g_Lacc[0][row] + g_Lacc[1][row]
               + g_Lacc[2][row] + g_Lacc[3][row];
    float inv = 1.0f / Lsum;

    // load 4 z-partials (16B each), all independent
    uint4 hz[ZSPLIT];
#pragma unroll
    for (int z = 0; z < ZSPLIT; z++)
        hz[z] = *reinterpret_cast<const uint4*>(&g_Oacc[z][(size_t)idx * 8]);

    float acc[8];
#pragma unroll
    for (int i = 0; i < 8; i++) acc[i] = 0.f;
#pragma unroll
    for (int z = 0; z < ZSPLIT; z++) {
        const uint32_t* hp = reinterpret_cast<const uint32_t*>(&hz[z]);
#pragma unroll
        for (int p = 0; p < 4; p++) {
            __half2 h = *reinterpret_cast<const __half2*>(&hp[p]);
            float2 f = __half22float2(h);
            acc[2 * p]     += f.x;
            acc[2 * p + 1] += f.y;
        }
    }

    float4 r0 = make_float4(acc[0] * inv, acc[1] * inv, acc[2] * inv, acc[3] * inv);
    float4 r1 = make_float4(acc[4] * inv, acc[5] * inv, acc[6] * inv, acc[7] * inv);
    *reinterpret_cast<float4*>(out + (size_t)idx * 8)     = r0;
    *reinterpret_cast<float4*>(out + (size_t)idx * 8 + 4) = r1;
}

// ============================================================================
extern "C" void kernel_launch(void* const* d_in, const int* in_sizes, int n_in,
                              void* d_out, int out_size)
{
    const float* q  = (const float*)d_in[0];
    const float* k  = (const float*)d_in[1];
    const float* v  = (const float*)d_in[2];
    const float* m  = (const float*)d_in[3];
    const float* Wq = (const float*)d_in[4];
    const float* bq = (const float*)d_in[5];
    const float* Wk = (const float*)d_in[6];
    const float* bk = (const float*)d_in[7];
    const float* Wv = (const float*)d_in[8];
    const float* bv = (const float*)d_in[9];
    float* out = (float*)d_out;

    cudaFuncSetAttribute(proj_all_kernel,
                         cudaFuncAttributeMaxDynamicSharedMemorySize, QK_SMEM);
    cudaFuncSetAttribute(attn_kernel,
                         cudaFuncAttributeMaxDynamicSharedMemorySize, ATTN_SMEM);

    dim3 wgrid(DMODEL * DK / 256, 3);
    wconv_kernel<<<wgrid, 256>>>(Wq, Wk, Wv);

    dim3 pgrid(ROWS / 64, 3);
    proj_all_kernel<<<pgrid, 128, QK_SMEM>>>(q, k, v, bq, bk, bv, m);

    dim3 grid(SEQ / BR, BATCH, ZSPLIT);
    attn_kernel<<<grid, 128, ATTN_SMEM>>>();

    normalize_kernel<<<ROWS * DK / 8 / 256, 256>>>(out);
}